// round 13
// baseline (speedup 1.0000x reference)
#include <cuda_runtime.h>

// conv2d 4096x4096 (fp32) * 15x15 VALID + bias -> 4082x4082 (fp32)
// R13: R12 (constant-memory weights, FFMA2 phase-shifted dual accumulators,
//      rolling staged window) with occupancy raised to 5 blocks/SM
//      (regs=46 fits the 51-reg cap; smem 5x24.4KB fits).

#define H 4096
#define W 4096
#define KH 15
#define KW 15
#define OH 4082
#define OW 4082

#define BX 192          // 16 threads * RX=12
#define BY 16
#define NT 256
#define RX 12           // 48B lane stride: odd multiple of 16B -> conflict-free

#define IN_H (BY + KH - 1)          // 30
#define SROW 208                    // pad 192+14 -> 208 (52 float4)

typedef unsigned long long ull;

__constant__ float cW[KH * KW];     // 225 floats, copied per launch (D2D memcpy node)

__device__ __forceinline__ ull pack2(float lo, float hi) {
    ull r; asm("mov.b64 %0, {%1, %2};" : "=l"(r) : "f"(lo), "f"(hi)); return r;
}
__device__ __forceinline__ void unpack2(ull v, float& lo, float& hi) {
    asm("mov.b64 {%0, %1}, %2;" : "=f"(lo), "=f"(hi) : "l"(v));
}
__device__ __forceinline__ ull fma2(ull a, ull b, ull c) {
    ull d; asm("fma.rn.f32x2 %0, %1, %2, %3;" : "=l"(d) : "l"(a), "l"(b), "l"(c)); return d;
}

__global__ __launch_bounds__(NT, 5)
void conv2d_r13_kernel(const float* __restrict__ X,
                       const float* __restrict__ bias,
                       float* __restrict__ out)
{
    __shared__ __align__(16) float sX[IN_H][SROW];

    const int tid = threadIdx.x;
    const int bx = blockIdx.x * BX;
    const int by = blockIdx.y * BY;

    // ---- stage input tile: 30 rows x 208 cols, float4, guarded ----
    const int NV = IN_H * (SROW / 4);     // 30*52 = 1560
    for (int idx = tid; idx < NV; idx += NT) {
        int r  = idx / (SROW / 4);
        int c4 = idx - r * (SROW / 4);
        int gr = by + r;
        int gc = bx + c4 * 4;
        float4 v = make_float4(0.f, 0.f, 0.f, 0.f);
        if (gr < H) {
            const float* src = X + (long)gr * W + gc;
            if (gc + 3 < W) v = *(const float4*)src;
            else {
                if (gc + 0 < W) v.x = src[0];
                if (gc + 1 < W) v.y = src[1];
                if (gc + 2 < W) v.z = src[2];
                if (gc + 3 < W) v.w = src[3];
            }
        }
        *(float4*)&sX[r][c4 * 4] = v;
    }
    __syncthreads();

    const int tx = tid & 15;
    const int ty = tid >> 4;
    const int ox = tx * RX;               // conflict-free, 16B aligned
    const float b0 = bias[0];

    ull accA[6];                          // (o_{2j}, o_{2j+1}); bias pre-folded
    ull accB[7];                          // (o_{2j-1}, o_{2j})
    {
        const ull bb = pack2(b0, b0);
        #pragma unroll
        for (int j = 0; j < 6; ++j) accA[j] = bb;
        #pragma unroll
        for (int j = 0; j < 7; ++j) accB[j] = 0ull;
    }

    #pragma unroll 1
    for (int ky = 0; ky < KH; ++ky) {
        const ulonglong2* row = (const ulonglong2*)&sX[ty + ky][ox];
        const float* rowf = &sX[ty + ky][ox];
        const int wb = ky * KW;

        // rolling window with staging lead:
        // v[0..3] up front; v4@c=0 (use c=2), v5@c=1 (use c=4), v6@c=2 (use c=6)
        ulonglong2 v[6];
        ull v6;
        v[0] = row[0]; v[1] = row[1]; v[2] = row[2]; v[3] = row[3];

        #pragma unroll
        for (int c = 0; c < 8; ++c) {
            if (c == 0) v[4] = row[4];
            if (c == 1) v[5] = row[5];
            if (c == 2) v6 = *(const ull*)(rowf + 24);   // P12 (8B suffices)

            // weights from the constant port (no L1 wavefronts)
            const float we = cW[wb + 2 * c];
            const ull wpx = pack2(we, we);
            // even tap a=2c: accA[j] += w_{2c} * P[j+c], j=0..5
            #pragma unroll
            for (int j = 0; j < 6; ++j) {
                const int p = j + c;
                const ull Pp = (p == 12) ? v6 : ((p & 1) ? v[p >> 1].y : v[p >> 1].x);
                accA[j] = fma2(wpx, Pp, accA[j]);
            }
            // odd tap a=2c+1: accB[j] += w_{2c+1} * P[j+c], j=0..6
            if (c < 7) {
                const float wo = cW[wb + 2 * c + 1];
                const ull wpy = pack2(wo, wo);
                #pragma unroll
                for (int j = 0; j < 7; ++j) {
                    const int p = j + c;
                    const ull Pp = (p == 12) ? v6 : ((p & 1) ? v[p >> 1].y : v[p >> 1].x);
                    accB[j] = fma2(wpy, Pp, accB[j]);
                }
            }
        }
    }

    // ---- epilogue: recombine phases, guarded float2 stores ----
    const int orow = by + ty;
    if (orow < OH) {
        float* orp = out + (long)orow * OW;
        float alo[6], ahi[6], blo[7], bhi[7];
        #pragma unroll
        for (int j = 0; j < 6; ++j) unpack2(accA[j], alo[j], ahi[j]);
        #pragma unroll
        for (int j = 0; j < 7; ++j) unpack2(accB[j], blo[j], bhi[j]);
        #pragma unroll
        for (int j = 0; j < 6; ++j) {
            int ocol = bx + ox + 2 * j;      // even; OW even -> pair fully in or out
            if (ocol < OW) {
                float2 st;
                st.x = alo[j] + bhi[j];          // o_{2j}   (bias in accA)
                st.y = ahi[j] + blo[j + 1];      // o_{2j+1}
                *(float2*)(orp + ocol) = st;
            }
        }
    }
}

extern "C" void kernel_launch(void* const* d_in, const int* in_sizes, int n_in,
                              void* d_out, int out_size)
{
    const float* X  = (const float*)d_in[0];
    const float* Wt = (const float*)d_in[1];
    const float* bs = (const float*)d_in[2];
    float* out = (float*)d_out;

    // weights -> constant bank (device-to-device async copy; graph-capturable)
    cudaMemcpyToSymbolAsync(cW, Wt, KH * KW * sizeof(float), 0,
                            cudaMemcpyDeviceToDevice, 0);

    dim3 grid((OW + BX - 1) / BX, (OH + BY - 1) / BY);   // 22 x 256
    conv2d_r13_kernel<<<grid, NT>>>(X, bs, out);
}